// round 12
// baseline (speedup 1.0000x reference)
#include <cuda_runtime.h>
#include <cuda_bf16.h>

#define NN 20000
#define DD 32
#define HH 64
#define GG 256
#define MT 48      // nodes per LSTM block
#define HSTR 50    // padded node stride (even for LDS.64, gcd(50,32)=2)

typedef unsigned long long u64;
typedef unsigned int u32;

// ---------------- device scratch (no allocations allowed) ----------------
__device__ int   g_nbrs[NN * DD];
__device__ float g_bufA[NN * HH];
__device__ float g_bufB[NN * HH];
__device__ float g_proj[NN * GG];
__device__ float g_agg [NN * HH];
__device__ float g_wT  [HH * GG];    // W_hh transposed: [k][g]

__device__ __forceinline__ float tanhx(float x) {
    float y; asm("tanh.approx.f32 %0, %1;" : "=f"(y) : "f"(x)); return y;
}
__device__ __forceinline__ float sigmx(float x) {
    return fmaf(tanhx(0.5f * x), 0.5f, 0.5f);
}
__device__ __forceinline__ u64 pack2(float lo, float hi) {
    u64 r;
    asm("mov.b64 %0, {%1, %2};" : "=l"(r) : "r"(__float_as_uint(lo)), "r"(__float_as_uint(hi)));
    return r;
}
__device__ __forceinline__ void unpack2(u64 v, float& lo, float& hi) {
    u32 a, b;
    asm("mov.b64 {%0, %1}, %2;" : "=r"(a), "=r"(b) : "l"(v));
    lo = __uint_as_float(a); hi = __uint_as_float(b);
}
__device__ __forceinline__ u64 fma2(u64 a, u64 b, u64 c) {
    u64 d;
    asm("fma.rn.f32x2 %0, %1, %2, %3;" : "=l"(d) : "l"(a), "l"(b), "l"(c));
    return d;
}

// ---------------- sort neighbor rows (bitonic, registers) ----------------
__global__ void sort_kernel(const int* __restrict__ nbr) {
    int node = blockIdx.x * blockDim.x + threadIdx.x;
    if (node >= NN) return;
    int v[DD];
#pragma unroll
    for (int i = 0; i < DD; i++) v[i] = nbr[node * DD + i];
#pragma unroll
    for (int k = 2; k <= DD; k <<= 1)
#pragma unroll
        for (int j = k >> 1; j > 0; j >>= 1)
#pragma unroll
            for (int i = 0; i < DD; i++) {
                int l = i ^ j;
                if (l > i) {
                    int a = v[i], b = v[l];
                    if ((a > b) == ((i & k) == 0)) { v[i] = b; v[l] = a; }
                }
            }
#pragma unroll
    for (int i = 0; i < DD; i++) g_nbrs[node * DD + i] = v[i];
}

// ---------------- transpose W_hh -> g_wT[k*256+g] -------------------------
__global__ void transw_kernel(const float* __restrict__ W) {
    int k = blockIdx.x, g = threadIdx.x;
    g_wT[k * GG + g] = W[g * HH + k];
}

// ---------------- proj = x @ W_ih^T + b_ih + b_hh  (32 nodes/block) -------
__global__ void proj_kernel(const float* __restrict__ x, int in_d,
                            const float* __restrict__ W_ih,
                            const float* __restrict__ b_ih,
                            const float* __restrict__ b_hh) {
    extern __shared__ float smf[];
    float* sW = smf;                 // [in_d][256] transposed
    float* sB = sW + in_d * GG;      // [256]
    float* sX = sB + GG;             // [32][in_d]
    int tid = threadIdx.x;
    for (int idx = tid; idx < in_d * GG; idx += 256) {
        int g = idx / in_d, k = idx - g * in_d;
        sW[k * GG + g] = W_ih[idx];
    }
    if (tid < GG) sB[tid] = b_ih[tid] + b_hh[tid];
    int node0 = blockIdx.x * 32;
    for (int idx = tid; idx < 32 * in_d; idx += 256) {
        int i = idx / in_d, k = idx - i * in_d;
        sX[idx] = x[(node0 + i) * in_d + k];
    }
    __syncthreads();
    int w = tid >> 5, tg = tid & 31;
    float acc[4][8];
#pragma unroll
    for (int i = 0; i < 4; i++)
#pragma unroll
        for (int j = 0; j < 8; j++) acc[i][j] = sB[tg + 32 * j];
    for (int k = 0; k < in_d; k++) {
        float xv[4];
#pragma unroll
        for (int i = 0; i < 4; i++) xv[i] = sX[(w * 4 + i) * in_d + k];
#pragma unroll
        for (int j = 0; j < 8; j++) {
            float b = sW[k * GG + tg + 32 * j];
#pragma unroll
            for (int i = 0; i < 4; i++) acc[i][j] += xv[i] * b;
        }
    }
#pragma unroll
    for (int i = 0; i < 4; i++) {
        int node = node0 + w * 4 + i;
#pragma unroll
        for (int j = 0; j < 8; j++) g_proj[node * GG + tg + 32 * j] = acc[i][j];
    }
}

// ---------------- LSTM recurrence (FFMA2, W from L1, occ 4) ---------------
// 192 threads (6 warps) x 48 nodes; warp owns 8 nodes, syncs only itself.
// c-state lives in thread-private SMEM slots -> regs <= 80 -> 4 CTAs/SM.
__global__ __launch_bounds__(192, 4)
void lstm_kernel() {
    __shared__ float sH[2 * HH * HSTR];   // 25.6 KB ping-pong h state
    __shared__ float sC[16 * 192];        // 12.3 KB thread-private c state
    int tid = threadIdx.x;
    int tg = tid & 31, tn = tid >> 5;
    for (int idx = tid; idx < 2 * HH * HSTR; idx += 192) sH[idx] = 0.f;
#pragma unroll
    for (int i = 0; i < 16; i++) sC[i * 192 + tid] = 0.f;   // private: no sync needed
    __syncthreads();

    int node0 = blockIdx.x * MT + tn * 8;
    int base = tn * 8;

    int p = 0;
#pragma unroll 1
    for (int t = 0; t < DD; t++) {
        u64 acc[8][4];   // [gate j][node-pair m]
#pragma unroll
        for (int m = 0; m < 4; m++) {
            int na = node0 + 2 * m, nb = na + 1;
            int ia = (na < NN) ? g_nbrs[na * DD + t] : 0;
            int ib = (nb < NN) ? g_nbrs[nb * DD + t] : 0;
            const float* pa = g_proj + (size_t)ia * GG + tg;
            const float* pb = g_proj + (size_t)ib * GG + tg;
#pragma unroll
            for (int j = 0; j < 8; j++)
                acc[j][m] = pack2(__ldg(&pa[32 * j]), __ldg(&pb[32 * j]));
        }
        if (t) {
            const float* sHr = sH + p * (HH * HSTR);
#pragma unroll 2
            for (int k = 0; k < HH; k++) {
                const float* wk = g_wT + k * GG + tg;
                u64 bb[8];
#pragma unroll
                for (int j = 0; j < 8; j++) {
                    float b = __ldg(&wk[32 * j]);
                    bb[j] = pack2(b, b);
                }
#pragma unroll
                for (int m = 0; m < 4; m++) {
                    u64 a2 = *(const u64*)(sHr + k * HSTR + base + 2 * m);  // uniform bcast
#pragma unroll
                    for (int j = 0; j < 8; j++) acc[j][m] = fma2(a2, bb[j], acc[j][m]);
                }
            }
        }
        float* sHw = sH + (p ^ 1) * (HH * HSTR);
        bool last = (t == DD - 1);
#pragma unroll
        for (int m = 0; m < 4; m++) {
            float ga[8], gb[8];
#pragma unroll
            for (int j = 0; j < 8; j++) unpack2(acc[j][m], ga[j], gb[j]);
            int ia = 2 * m, ib = 2 * m + 1;
            // node a = 2m  (c0 at slot ia, c1 at slot 8+ia)
            float ca0 = sC[ia * 192 + tid], ca1 = sC[(8 + ia) * 192 + tid];
            ca0 = sigmx(ga[2]) * ca0 + sigmx(ga[0]) * tanhx(ga[4]);
            ca1 = sigmx(ga[3]) * ca1 + sigmx(ga[1]) * tanhx(ga[5]);
            sC[ia * 192 + tid] = ca0;
            sC[(8 + ia) * 192 + tid] = ca1;
            float h0a = sigmx(ga[6]) * tanhx(ca0);
            float h1a = sigmx(ga[7]) * tanhx(ca1);
            // node b = 2m+1
            float cb0 = sC[ib * 192 + tid], cb1 = sC[(8 + ib) * 192 + tid];
            cb0 = sigmx(gb[2]) * cb0 + sigmx(gb[0]) * tanhx(gb[4]);
            cb1 = sigmx(gb[3]) * cb1 + sigmx(gb[1]) * tanhx(gb[5]);
            sC[ib * 192 + tid] = cb0;
            sC[(8 + ib) * 192 + tid] = cb1;
            float h0b = sigmx(gb[6]) * tanhx(cb0);
            float h1b = sigmx(gb[7]) * tanhx(cb1);
            if (!last) {
                *(float2*)(sHw + tg * HSTR + base + 2 * m)        = make_float2(h0a, h0b);
                *(float2*)(sHw + (tg + 32) * HSTR + base + 2 * m) = make_float2(h1a, h1b);
            } else {
                int na = node0 + 2 * m, nb = na + 1;
                if (na < NN) {
                    g_agg[na * HH + tg]      = h0a;
                    g_agg[na * HH + tg + 32] = h1a;
                }
                if (nb < NN) {
                    g_agg[nb * HH + tg]      = h0b;
                    g_agg[nb * HH + tg + 32] = h1b;
                }
            }
        }
        __syncwarp();
        p ^= 1;
    }
}

// ---------------- h_next = relu([x, agg] @ Wl^T + bl)  (32 nodes/block) ---
__global__ void combine_kernel(const float* __restrict__ x, int in_d,
                               const float* __restrict__ Wl,
                               const float* __restrict__ bl,
                               float* __restrict__ out) {
    extern __shared__ float smf[];
    int C = in_d + HH;
    float* sW = smf;           // [C][64] transposed
    float* sB = sW + C * HH;   // [64]
    float* sX = sB + HH;       // [32][C]
    int tid = threadIdx.x;
    for (int idx = tid; idx < C * HH; idx += 256) {
        int o = idx / C, k = idx - o * C;
        sW[k * HH + o] = Wl[idx];
    }
    if (tid < HH) sB[tid] = bl[tid];
    int node0 = blockIdx.x * 32;
    for (int idx = tid; idx < 32 * C; idx += 256) {
        int i = idx / C, k = idx - i * C;
        sX[idx] = (k < in_d) ? x[(node0 + i) * in_d + k]
                             : g_agg[(node0 + i) * HH + (k - in_d)];
    }
    __syncthreads();
    int w = tid >> 5, tg = tid & 31;
    u64 acc[4];
#pragma unroll
    for (int i = 0; i < 4; i++) acc[i] = *(const u64*)(sB + 2 * tg);
    for (int k = 0; k < C; k++) {
        u64 wp = *(const u64*)(sW + k * HH + 2 * tg);
#pragma unroll
        for (int i = 0; i < 4; i++) {
            float xv = sX[(w * 4 + i) * C + k];
            acc[i] = fma2(pack2(xv, xv), wp, acc[i]);
        }
    }
#pragma unroll
    for (int i = 0; i < 4; i++) {
        float a0, a1;
        unpack2(acc[i], a0, a1);
        int node = node0 + w * 4 + i;
        *(float2*)(out + node * HH + 2 * tg) = make_float2(fmaxf(a0, 0.f), fmaxf(a1, 0.f));
    }
}

// ---------------- out = h @ W_out^T + b_out -------------------------------
__global__ void out_kernel(const float* __restrict__ h,
                           const float* __restrict__ W_out,
                           const float* __restrict__ b_out,
                           float* __restrict__ out) {
    int tid = threadIdx.x;
    int node = blockIdx.x * 8 + (tid >> 5);
    int tg = tid & 31;
    float a = h[node * HH + tg] * W_out[tg] + h[node * HH + tg + 32] * W_out[tg + 32];
#pragma unroll
    for (int s = 16; s > 0; s >>= 1) a += __shfl_down_sync(0xffffffffu, a, s);
    if (tg == 0) out[node] = a + b_out[0];
}

// ---------------- launcher ------------------------------------------------
extern "C" void kernel_launch(void* const* d_in, const int* in_sizes, int n_in,
                              void* d_out, int out_size) {
    const float* node_features = (const float*)d_in[0];
    const int*   nbr           = (const int*)d_in[1];
    const float *W_ih[3], *W_hh[3], *b_ih[3], *b_hh[3], *Wl[3], *bl[3];
    for (int l = 0; l < 3; l++) {
        W_ih[l] = (const float*)d_in[2 + 6 * l + 0];
        W_hh[l] = (const float*)d_in[2 + 6 * l + 1];
        b_ih[l] = (const float*)d_in[2 + 6 * l + 2];
        b_hh[l] = (const float*)d_in[2 + 6 * l + 3];
        Wl[l]   = (const float*)d_in[2 + 6 * l + 4];
        bl[l]   = (const float*)d_in[2 + 6 * l + 5];
    }
    const float* W_out = (const float*)d_in[20];
    const float* b_out = (const float*)d_in[21];
    float* out = (float*)d_out;

    float *bufA, *bufB;
    cudaGetSymbolAddress((void**)&bufA, g_bufA);
    cudaGetSymbolAddress((void**)&bufB, g_bufB);

    cudaFuncSetAttribute(proj_kernel, cudaFuncAttributeMaxDynamicSharedMemorySize, 80000);
    cudaFuncSetAttribute(combine_kernel, cudaFuncAttributeMaxDynamicSharedMemorySize, 56000);

    sort_kernel<<<(NN + 255) / 256, 256>>>(nbr);

    const float* x = node_features;
    float* nxt = bufA;
    int grid_lstm = (NN + MT - 1) / MT;   // 417
    for (int l = 0; l < 3; l++) {
        int in_d = (l == 0) ? 3 : 64;
        size_t proj_sm = (size_t)(in_d * GG + GG + 32 * in_d) * 4;
        transw_kernel<<<HH, GG>>>(W_hh[l]);
        proj_kernel<<<NN / 32, 256, proj_sm>>>(x, in_d, W_ih[l], b_ih[l], b_hh[l]);
        lstm_kernel<<<grid_lstm, 192>>>();
        int C = in_d + HH;
        size_t comb_sm = (size_t)(C * HH + HH + 32 * C) * 4;
        combine_kernel<<<NN / 32, 256, comb_sm>>>(x, in_d, Wl[l], bl[l], nxt);
        x = nxt;
        nxt = (nxt == bufA) ? bufB : bufA;
    }
    out_kernel<<<NN / 8, 256>>>(x, W_out, b_out, out);
}

// round 14
// speedup vs baseline: 1.9721x; 1.9721x over previous
#include <cuda_runtime.h>
#include <cuda_bf16.h>

#define NN 20000
#define DD 32
#define HH 64
#define GG 256
#define MT 48      // nodes per LSTM block
#define HSTR 52    // padded node stride (stride 208B: 16B-aligned for LDS.128)

typedef unsigned long long u64;
typedef unsigned int u32;

// ---------------- device scratch (no allocations allowed) ----------------
__device__ int   g_nbrs[NN * DD];
__device__ float g_bufA[NN * HH];
__device__ float g_bufB[NN * HH];
__device__ float g_proj[NN * GG];
__device__ float g_agg [NN * HH];
__device__ u64   g_wPK [HH * 128];   // packed W_hh: [k][jp*32+tg] = (w[64jp+tg][k], w[64jp+tg+32][k])

__device__ __forceinline__ float tanhx(float x) {
    float y; asm("tanh.approx.f32 %0, %1;" : "=f"(y) : "f"(x)); return y;
}
__device__ __forceinline__ float sigmx(float x) {
    return fmaf(tanhx(0.5f * x), 0.5f, 0.5f);
}
__device__ __forceinline__ u64 pack2(float lo, float hi) {
    u64 r;
    asm("mov.b64 %0, {%1, %2};" : "=l"(r) : "r"(__float_as_uint(lo)), "r"(__float_as_uint(hi)));
    return r;
}
__device__ __forceinline__ void unpack2(u64 v, float& lo, float& hi) {
    u32 a, b;
    asm("mov.b64 {%0, %1}, %2;" : "=r"(a), "=r"(b) : "l"(v));
    lo = __uint_as_float(a); hi = __uint_as_float(b);
}
__device__ __forceinline__ u64 fma2(u64 a, u64 b, u64 c) {
    u64 d;
    asm("fma.rn.f32x2 %0, %1, %2, %3;" : "=l"(d) : "l"(a), "l"(b), "l"(c));
    return d;
}

// ---------------- sort neighbor rows (bitonic, registers) ----------------
__global__ void sort_kernel(const int* __restrict__ nbr) {
    int node = blockIdx.x * blockDim.x + threadIdx.x;
    if (node >= NN) return;
    int v[DD];
#pragma unroll
    for (int i = 0; i < DD; i++) v[i] = nbr[node * DD + i];
#pragma unroll
    for (int k = 2; k <= DD; k <<= 1)
#pragma unroll
        for (int j = k >> 1; j > 0; j >>= 1)
#pragma unroll
            for (int i = 0; i < DD; i++) {
                int l = i ^ j;
                if (l > i) {
                    int a = v[i], b = v[l];
                    if ((a > b) == ((i & k) == 0)) { v[i] = b; v[l] = a; }
                }
            }
#pragma unroll
    for (int i = 0; i < DD; i++) g_nbrs[node * DD + i] = v[i];
}

// ---------------- pack W_hh -> g_wPK[k][jp*32+tg] -------------------------
__global__ void packw_kernel(const float* __restrict__ W) {
    int k = blockIdx.x, g = threadIdx.x;        // g in [0,128)
    int jp = g >> 5, tg = g & 31;
    float w0 = W[(64 * jp + tg) * HH + k];
    float w1 = W[(64 * jp + tg + 32) * HH + k];
    g_wPK[k * 128 + g] = pack2(w0, w1);
}

// ---------------- proj = x @ W_ih^T + b_ih + b_hh  (32 nodes/block) -------
__global__ void proj_kernel(const float* __restrict__ x, int in_d,
                            const float* __restrict__ W_ih,
                            const float* __restrict__ b_ih,
                            const float* __restrict__ b_hh) {
    extern __shared__ float smf[];
    float* sW = smf;                 // [in_d][256] transposed
    float* sB = sW + in_d * GG;      // [256]
    float* sX = sB + GG;             // [32][in_d]
    int tid = threadIdx.x;
    for (int idx = tid; idx < in_d * GG; idx += 256) {
        int g = idx / in_d, k = idx - g * in_d;
        sW[k * GG + g] = W_ih[idx];
    }
    if (tid < GG) sB[tid] = b_ih[tid] + b_hh[tid];
    int node0 = blockIdx.x * 32;
    for (int idx = tid; idx < 32 * in_d; idx += 256) {
        int i = idx / in_d, k = idx - i * in_d;
        sX[idx] = x[(node0 + i) * in_d + k];
    }
    __syncthreads();
    int w = tid >> 5, tg = tid & 31;
    float acc[4][8];
#pragma unroll
    for (int i = 0; i < 4; i++)
#pragma unroll
        for (int j = 0; j < 8; j++) acc[i][j] = sB[tg + 32 * j];
    for (int k = 0; k < in_d; k++) {
        float xv[4];
#pragma unroll
        for (int i = 0; i < 4; i++) xv[i] = sX[(w * 4 + i) * in_d + k];
#pragma unroll
        for (int j = 0; j < 8; j++) {
            float b = sW[k * GG + tg + 32 * j];
#pragma unroll
            for (int i = 0; i < 4; i++) acc[i][j] += xv[i] * b;
        }
    }
#pragma unroll
    for (int i = 0; i < 4; i++) {
        int node = node0 + w * 4 + i;
#pragma unroll
        for (int j = 0; j < 8; j++) g_proj[node * GG + tg + 32 * j] = acc[i][j];
    }
}

// ---------------- LSTM recurrence (FFMA2, packed weights, occ 3) ----------
// 192 threads (6 warps) x 48 nodes; warp owns 8 nodes, syncs only itself.
// acc[jp][node]: halves = gate jp of hidden tg / tg+32. Weights arrive as
// pre-packed u64 (LDG.64 -> fma2 direct, no pack). h is scalar-dup packed.
__global__ __launch_bounds__(192, 3)
void lstm_kernel() {
    __shared__ float sH[2 * HH * HSTR];   // ping-pong h state, 26.6 KB
    int tid = threadIdx.x;
    int tg = tid & 31, tn = tid >> 5;
    for (int idx = tid; idx < 2 * HH * HSTR; idx += 192) sH[idx] = 0.f;
    __syncthreads();

    int node0 = blockIdx.x * MT + tn * 8;
    int base = tn * 8;
    float c0[8], c1[8];
#pragma unroll
    for (int i = 0; i < 8; i++) { c0[i] = 0.f; c1[i] = 0.f; }

    int p = 0;
#pragma unroll 1
    for (int t = 0; t < DD; t++) {
        u64 acc[4][8];   // [gate-pair jp][node i]
        // gather: proj of t-th sorted neighbor; pair = (gate jp of tg, of tg+32)
#pragma unroll
        for (int i = 0; i < 8; i++) {
            int n = node0 + i;
            int nb = (n < NN) ? g_nbrs[n * DD + t] : 0;
            const float* pr = g_proj + (size_t)nb * GG + tg;
#pragma unroll
            for (int jp = 0; jp < 4; jp++)
                acc[jp][i] = pack2(__ldg(&pr[64 * jp]), __ldg(&pr[64 * jp + 32]));
        }
        if (t) {
            const float* sHr = sH + p * (HH * HSTR) + base;
#pragma unroll 2
            for (int k = 0; k < HH; k++) {
                const u64* wk = g_wPK + k * 128 + tg;
                u64 b0 = __ldg(wk);
                u64 b1 = __ldg(wk + 32);
                u64 b2 = __ldg(wk + 64);
                u64 b3 = __ldg(wk + 96);
                float4 q0 = *(const float4*)(sHr + k * HSTR);       // h nodes 0..3 (bcast)
                float4 q1 = *(const float4*)(sHr + k * HSTR + 4);   // h nodes 4..7
                u64 a0 = pack2(q0.x, q0.x), a1 = pack2(q0.y, q0.y);
                u64 a2 = pack2(q0.z, q0.z), a3 = pack2(q0.w, q0.w);
                u64 a4 = pack2(q1.x, q1.x), a5 = pack2(q1.y, q1.y);
                u64 a6 = pack2(q1.z, q1.z), a7 = pack2(q1.w, q1.w);
                acc[0][0] = fma2(a0, b0, acc[0][0]); acc[1][0] = fma2(a0, b1, acc[1][0]);
                acc[2][0] = fma2(a0, b2, acc[2][0]); acc[3][0] = fma2(a0, b3, acc[3][0]);
                acc[0][1] = fma2(a1, b0, acc[0][1]); acc[1][1] = fma2(a1, b1, acc[1][1]);
                acc[2][1] = fma2(a1, b2, acc[2][1]); acc[3][1] = fma2(a1, b3, acc[3][1]);
                acc[0][2] = fma2(a2, b0, acc[0][2]); acc[1][2] = fma2(a2, b1, acc[1][2]);
                acc[2][2] = fma2(a2, b2, acc[2][2]); acc[3][2] = fma2(a2, b3, acc[3][2]);
                acc[0][3] = fma2(a3, b0, acc[0][3]); acc[1][3] = fma2(a3, b1, acc[1][3]);
                acc[2][3] = fma2(a3, b2, acc[2][3]); acc[3][3] = fma2(a3, b3, acc[3][3]);
                acc[0][4] = fma2(a4, b0, acc[0][4]); acc[1][4] = fma2(a4, b1, acc[1][4]);
                acc[2][4] = fma2(a4, b2, acc[2][4]); acc[3][4] = fma2(a4, b3, acc[3][4]);
                acc[0][5] = fma2(a5, b0, acc[0][5]); acc[1][5] = fma2(a5, b1, acc[1][5]);
                acc[2][5] = fma2(a5, b2, acc[2][5]); acc[3][5] = fma2(a5, b3, acc[3][5]);
                acc[0][6] = fma2(a6, b0, acc[0][6]); acc[1][6] = fma2(a6, b1, acc[1][6]);
                acc[2][6] = fma2(a6, b2, acc[2][6]); acc[3][6] = fma2(a6, b3, acc[3][6]);
                acc[0][7] = fma2(a7, b0, acc[0][7]); acc[1][7] = fma2(a7, b1, acc[1][7]);
                acc[2][7] = fma2(a7, b2, acc[2][7]); acc[3][7] = fma2(a7, b3, acc[3][7]);
            }
        }
        // cell update: acc[jp][i] halves = gate jp for hidden tg (lo), tg+32 (hi)
        float* sHw = sH + (p ^ 1) * (HH * HSTR);
        bool last = (t == DD - 1);
#pragma unroll
        for (int m = 0; m < 4; m++) {
            int i0 = 2 * m, i1 = 2 * m + 1;
            float ia0, ia1, fa0, fa1, ga0, ga1, oa0, oa1;
            float ib0, ib1, fb0, fb1, gb0, gb1, ob0, ob1;
            unpack2(acc[0][i0], ia0, ia1); unpack2(acc[1][i0], fa0, fa1);
            unpack2(acc[2][i0], ga0, ga1); unpack2(acc[3][i0], oa0, oa1);
            unpack2(acc[0][i1], ib0, ib1); unpack2(acc[1][i1], fb0, fb1);
            unpack2(acc[2][i1], gb0, gb1); unpack2(acc[3][i1], ob0, ob1);
            c0[i0] = sigmx(fa0) * c0[i0] + sigmx(ia0) * tanhx(ga0);
            c1[i0] = sigmx(fa1) * c1[i0] + sigmx(ia1) * tanhx(ga1);
            float h0a = sigmx(oa0) * tanhx(c0[i0]);
            float h1a = sigmx(oa1) * tanhx(c1[i0]);
            c0[i1] = sigmx(fb0) * c0[i1] + sigmx(ib0) * tanhx(gb0);
            c1[i1] = sigmx(fb1) * c1[i1] + sigmx(ib1) * tanhx(gb1);
            float h0b = sigmx(ob0) * tanhx(c0[i1]);
            float h1b = sigmx(ob1) * tanhx(c1[i1]);
            if (!last) {
                *(float2*)(sHw + tg * HSTR + base + 2 * m)        = make_float2(h0a, h0b);
                *(float2*)(sHw + (tg + 32) * HSTR + base + 2 * m) = make_float2(h1a, h1b);
            } else {
                int na = node0 + i0, nb = na + 1;
                if (na < NN) {
                    g_agg[na * HH + tg]      = h0a;
                    g_agg[na * HH + tg + 32] = h1a;
                }
                if (nb < NN) {
                    g_agg[nb * HH + tg]      = h0b;
                    g_agg[nb * HH + tg + 32] = h1b;
                }
            }
        }
        __syncwarp();
        p ^= 1;
    }
}

// ---------------- h_next = relu([x, agg] @ Wl^T + bl)  (32 nodes/block) ---
__global__ void combine_kernel(const float* __restrict__ x, int in_d,
                               const float* __restrict__ Wl,
                               const float* __restrict__ bl,
                               float* __restrict__ out) {
    extern __shared__ float smf[];
    int C = in_d + HH;
    float* sW = smf;           // [C][64] transposed
    float* sB = sW + C * HH;   // [64]
    float* sX = sB + HH;       // [32][C]
    int tid = threadIdx.x;
    for (int idx = tid; idx < C * HH; idx += 256) {
        int o = idx / C, k = idx - o * C;
        sW[k * HH + o] = Wl[idx];
    }
    if (tid < HH) sB[tid] = bl[tid];
    int node0 = blockIdx.x * 32;
    for (int idx = tid; idx < 32 * C; idx += 256) {
        int i = idx / C, k = idx - i * C;
        sX[idx] = (k < in_d) ? x[(node0 + i) * in_d + k]
                             : g_agg[(node0 + i) * HH + (k - in_d)];
    }
    __syncthreads();
    int w = tid >> 5, tg = tid & 31;
    u64 acc[4];
#pragma unroll
    for (int i = 0; i < 4; i++) acc[i] = *(const u64*)(sB + 2 * tg);
    for (int k = 0; k < C; k++) {
        u64 wp = *(const u64*)(sW + k * HH + 2 * tg);
#pragma unroll
        for (int i = 0; i < 4; i++) {
            float xv = sX[(w * 4 + i) * C + k];
            acc[i] = fma2(pack2(xv, xv), wp, acc[i]);
        }
    }
#pragma unroll
    for (int i = 0; i < 4; i++) {
        float a0, a1;
        unpack2(acc[i], a0, a1);
        int node = node0 + w * 4 + i;
        *(float2*)(out + node * HH + 2 * tg) = make_float2(fmaxf(a0, 0.f), fmaxf(a1, 0.f));
    }
}

// ---------------- out = h @ W_out^T + b_out -------------------------------
__global__ void out_kernel(const float* __restrict__ h,
                           const float* __restrict__ W_out,
                           const float* __restrict__ b_out,
                           float* __restrict__ out) {
    int tid = threadIdx.x;
    int node = blockIdx.x * 8 + (tid >> 5);
    int tg = tid & 31;
    float a = h[node * HH + tg] * W_out[tg] + h[node * HH + tg + 32] * W_out[tg + 32];
#pragma unroll
    for (int s = 16; s > 0; s >>= 1) a += __shfl_down_sync(0xffffffffu, a, s);
    if (tg == 0) out[node] = a + b_out[0];
}

// ---------------- launcher ------------------------------------------------
extern "C" void kernel_launch(void* const* d_in, const int* in_sizes, int n_in,
                              void* d_out, int out_size) {
    const float* node_features = (const float*)d_in[0];
    const int*   nbr           = (const int*)d_in[1];
    const float *W_ih[3], *W_hh[3], *b_ih[3], *b_hh[3], *Wl[3], *bl[3];
    for (int l = 0; l < 3; l++) {
        W_ih[l] = (const float*)d_in[2 + 6 * l + 0];
        W_hh[l] = (const float*)d_in[2 + 6 * l + 1];
        b_ih[l] = (const float*)d_in[2 + 6 * l + 2];
        b_hh[l] = (const float*)d_in[2 + 6 * l + 3];
        Wl[l]   = (const float*)d_in[2 + 6 * l + 4];
        bl[l]   = (const float*)d_in[2 + 6 * l + 5];
    }
    const float* W_out = (const float*)d_in[20];
    const float* b_out = (const float*)d_in[21];
    float* out = (float*)d_out;

    float *bufA, *bufB;
    cudaGetSymbolAddress((void**)&bufA, g_bufA);
    cudaGetSymbolAddress((void**)&bufB, g_bufB);

    cudaFuncSetAttribute(proj_kernel, cudaFuncAttributeMaxDynamicSharedMemorySize, 80000);
    cudaFuncSetAttribute(combine_kernel, cudaFuncAttributeMaxDynamicSharedMemorySize, 56000);

    sort_kernel<<<(NN + 255) / 256, 256>>>(nbr);

    const float* x = node_features;
    float* nxt = bufA;
    int grid_lstm = (NN + MT - 1) / MT;   // 417
    for (int l = 0; l < 3; l++) {
        int in_d = (l == 0) ? 3 : 64;
        size_t proj_sm = (size_t)(in_d * GG + GG + 32 * in_d) * 4;
        packw_kernel<<<HH, 128>>>(W_hh[l]);
        proj_kernel<<<NN / 32, 256, proj_sm>>>(x, in_d, W_ih[l], b_ih[l], b_hh[l]);
        lstm_kernel<<<grid_lstm, 192>>>();
        int C = in_d + HH;
        size_t comb_sm = (size_t)(C * HH + HH + 32 * C) * 4;
        combine_kernel<<<NN / 32, 256, comb_sm>>>(x, in_d, Wl[l], bl[l], nxt);
        x = nxt;
        nxt = (nxt == bufA) ? bufB : bufA;
    }
    out_kernel<<<NN / 8, 256>>>(x, W_out, b_out, out);
}